// round 7
// baseline (speedup 1.0000x reference)
#include <cuda_runtime.h>
#include <math.h>

namespace {
constexpr int Bc = 4, Nc = 2048, Ec = 768, Hc = 12, Dc = 64;
}

// Scratch (allocation-free rule: __device__ globals)
__device__ float g_qh[(size_t)Bc * Hc * Nc * Dc];
__device__ float g_kh[(size_t)Bc * Hc * Nc * Dc];
__device__ float g_vh[(size_t)Bc * Hc * Nc * Dc];
__device__ float g_att[(size_t)Bc * Nc * Ec];

// ---------------- f32x2 helpers (packed fp32 pair in u64) ----------------
__device__ __forceinline__ void fma2(unsigned long long& d,
                                     unsigned long long a, unsigned long long b) {
    asm("fma.rn.f32x2 %0, %1, %2, %0;" : "+l"(d) : "l"(a), "l"(b));
}
__device__ __forceinline__ void mul2(unsigned long long& d, unsigned long long b) {
    asm("mul.rn.f32x2 %0, %0, %1;" : "+l"(d) : "l"(b));
}
__device__ __forceinline__ unsigned long long pk2(float lo, float hi) {
    unsigned long long r;
    asm("mov.b64 %0, {%1, %2};" : "=l"(r) : "f"(lo), "f"(hi));
    return r;
}
__device__ __forceinline__ unsigned long long dup2(float x) {
    unsigned int u = __float_as_uint(x);
    return ((unsigned long long)u << 32) | (unsigned long long)u;
}
__device__ __forceinline__ float2 u2f(unsigned long long v) {
    float2 r;
    r.x = __uint_as_float((unsigned int)v);
    r.y = __uint_as_float((unsigned int)(v >> 32));
    return r;
}

// ---------------------------------------------------------------------------
// Kernel 1: RMSNorm + xPos RoPE + head-split transpose. One warp per (b,n,h).
// Folds (1/sqrt(D)) * log2(e) into Q so softmax can use exp2f.
// ---------------------------------------------------------------------------
__global__ void prep_kernel(const float* __restrict__ q, const float* __restrict__ k,
                            const float* __restrict__ v,
                            const float* __restrict__ qs, const float* __restrict__ ks) {
    int w = (blockIdx.x * blockDim.x + threadIdx.x) >> 5;
    int lane = threadIdx.x & 31;
    if (w >= Bc * Nc * Hc) return;
    int h = w % Hc;
    int bn = w / Hc;
    int n = bn % Nc;
    int b = bn / Nc;

    size_t in_off = (size_t)bn * Ec + h * Dc;
    int d0 = lane, d1 = lane + 32;

    float q0 = q[in_off + d0], q1 = q[in_off + d1];
    float k0 = k[in_off + d0], k1 = k[in_off + d1];
    float v0 = v[in_off + d0], v1 = v[in_off + d1];

    float sq = q0 * q0 + q1 * q1;
    float sk = k0 * k0 + k1 * k1;
#pragma unroll
    for (int o = 16; o; o >>= 1) {
        sq += __shfl_xor_sync(0xffffffffu, sq, o);
        sk += __shfl_xor_sync(0xffffffffu, sk, o);
    }
    float qn = rsqrtf(sq * (1.0f / 64.0f) + 1e-6f);
    float kn = rsqrtf(sk * (1.0f / 64.0f) + 1e-6f);
    q0 *= qs[d0] * qn; q1 *= qs[d1] * qn;
    k0 *= ks[d0] * kn; k1 *= ks[d1] * kn;

    // xPos RoPE on dims [0,32)
    int p = d0 >> 1;
    double invf = pow(10000.0, -(double)p / 16.0);
    double fr = (double)n * invf;
    float c = (float)cos(fr), s = (float)sin(fr);
    double base = (2.0 * p + 12.8) / 44.8;
    double pw = ((double)n - 1024.0) / 512.0;
    float sc = (float)pow(base, pw);

    float qp_ = __shfl_xor_sync(0xffffffffu, q0, 1);
    float kp_ = __shfl_xor_sync(0xffffffffu, k0, 1);
    float sgn = (d0 & 1) ? s : -s;
    q0 = (q0 * c + qp_ * sgn) * sc;
    k0 = (k0 * c + kp_ * sgn) / sc;

    // fold softmax scale 1/sqrt(64) AND log2(e) into Q (exp2 softmax)
    const float QSCL = 0.125f * 1.4426950408889634f;
    q0 *= QSCL; q1 *= QSCL;

    size_t out_off = (((size_t)(b * Hc + h)) * Nc + n) * Dc;
    g_qh[out_off + d0] = q0; g_qh[out_off + d1] = q1;
    g_kh[out_off + d0] = k0; g_kh[out_off + d1] = k1;
    g_vh[out_off + d0] = v0; g_vh[out_off + d1] = v1;
}

// ---------------------------------------------------------------------------
// Kernel 2: causal flash attention, fp32x2 packed FMA.
// Block = 256 thr (16x16), block tile 128x128, micro tile 8x8 (row-paired).
// SMEM layouts (all hot accesses are 16B*tx conflict-free):
//   Qd   [64 d][132 rows]       floats, row-pairs read as ulonglong2 (broadcast)
//   Kdup [64 d][130]            u64 dup'd K values, plane-split over col pairs
//   Vdup [128 j][64]            u64 dup'd V values, plane-split over d pairs
//   Ps2  [64 rowpair][128 j]    u64 row-paired P, plane-split over j pairs
// ---------------------------------------------------------------------------
__global__ __launch_bounds__(256, 1) void attn_kernel() {
    extern __shared__ char smc[];
    float* Qd = (float*)smc;                                          // 33792 B
    unsigned long long* Kdup = (unsigned long long*)(smc + 33792);    // 66560 B
    unsigned long long* Vdup = Kdup + 64 * 130;                       // 65536 B
    unsigned long long* Ps2  = Vdup + 128 * 64;                       // 65536 B

    int qi = (int)gridDim.x - 1 - (int)blockIdx.x;   // big tiles first
    int bh = blockIdx.y;
    int bb = bh / Hc, h = bh % Hc;
    int tid = threadIdx.x;
    int tx = tid & 15, ty = tid >> 4;

    size_t base = (size_t)bh * Nc * Dc;
    const float* Qg = g_qh + base + (size_t)qi * 128 * Dc;

    // load Q tile (once), d-major transpose; stride 132 breaks store conflicts
#pragma unroll 8
    for (int it = 0; it < 32; it++) {
        int idx = it * 256 + tid;
        int row = idx >> 6, d = idx & 63;
        Qd[d * 132 + row] = Qg[row * 64 + d];
    }

    float m[8], l[8];
    unsigned long long acc2[4][4];   // O acc: [rowpair][d], rows (8ty+2i, 8ty+2i+1)
#pragma unroll
    for (int r = 0; r < 8; r++) { m[r] = -INFINITY; l[r] = 0.f; }
#pragma unroll
    for (int i = 0; i < 4; i++)
#pragma unroll
        for (int d = 0; d < 4; d++) acc2[i][d] = 0ull;

    const float* qp = Qd + 8 * ty;
    const unsigned long long* kp = Kdup + 2 * tx;
    const unsigned long long* pp0 = Ps2 + (4 * ty + 0) * 128;
    const unsigned long long* pp1 = Ps2 + (4 * ty + 1) * 128;
    const unsigned long long* pp2 = Ps2 + (4 * ty + 2) * 128;
    const unsigned long long* pp3 = Ps2 + (4 * ty + 3) * 128;
    const unsigned long long* vp = Vdup + 2 * tx;
    unsigned long long* psw = Ps2 + 2 * tx;   // write base, + (4ty+i)*128 + s*32

    for (int kt = 0; kt <= qi; kt++) {
        const float* Kg = g_kh + base + (size_t)kt * 128 * Dc;
        const float* Vg = g_vh + base + (size_t)kt * 128 * Dc;
        // fill K (dup'd, plane-split over col pairs) and V (dup'd, plane-split over d pairs)
#pragma unroll 4
        for (int it = 0; it < 32; it++) {
            int idx = it * 256 + tid;
            int j = idx >> 6, d = idx & 63;
            float kv = Kg[j * 64 + d];
            float vv = Vg[j * 64 + d];
            Kdup[d * 130 + ((j >> 1) & 3) * 32 + ((j >> 3) << 1) + (j & 1)] = dup2(kv);
            Vdup[j * 64 + ((d >> 1) & 1) * 32 + ((d >> 2) << 1) + (d & 1)] = dup2(vv);
        }
        __syncthreads();

        // ---- S = Q K^T : acc s2[rowpair i][col c], rows (2i,2i+1)+8ty, col 8tx+c
        unsigned long long s2[4][8];
#pragma unroll
        for (int i = 0; i < 4; i++)
#pragma unroll
            for (int c = 0; c < 8; c++) s2[i][c] = 0ull;

#pragma unroll 4
        for (int kk = 0; kk < 64; kk++) {
            ulonglong2 qa = *(const ulonglong2*)(qp + kk * 132);
            ulonglong2 qb = *(const ulonglong2*)(qp + kk * 132 + 4);
            const unsigned long long* kr = kp + kk * 130;
            ulonglong2 k0 = *(const ulonglong2*)(kr);
            ulonglong2 k1 = *(const ulonglong2*)(kr + 32);
            ulonglong2 k2 = *(const ulonglong2*)(kr + 64);
            ulonglong2 k3 = *(const ulonglong2*)(kr + 96);
            unsigned long long a0 = qa.x, a1 = qa.y, a2 = qb.x, a3 = qb.y;
            unsigned long long bz[8] = {k0.x, k0.y, k1.x, k1.y, k2.x, k2.y, k3.x, k3.y};
#pragma unroll
            for (int c = 0; c < 8; c++) {
                fma2(s2[0][c], a0, bz[c]);
                fma2(s2[1][c], a1, bz[c]);
                fma2(s2[2][c], a2, bz[c]);
                fma2(s2[3][c], a3, bz[c]);
            }
        }

        // ---- unpack scores
        float sv[8][8];
#pragma unroll
        for (int i = 0; i < 4; i++)
#pragma unroll
            for (int c = 0; c < 8; c++) {
                float2 f = u2f(s2[i][c]);
                sv[2 * i][c] = f.x;
                sv[2 * i + 1][c] = f.y;
            }

        if (kt == qi) {   // causal mask on diagonal tile
            int rb = 8 * ty, cb = 8 * tx;
#pragma unroll
            for (int r = 0; r < 8; r++)
#pragma unroll
                for (int c = 0; c < 8; c++)
                    if (cb + c > rb + r) sv[r][c] = -INFINITY;
        }

        // ---- online softmax (base-2; log2e folded into Q)
        float fac[8];
#pragma unroll
        for (int r = 0; r < 8; r++) {
            float mx = fmaxf(fmaxf(fmaxf(sv[r][0], sv[r][1]), fmaxf(sv[r][2], sv[r][3])),
                             fmaxf(fmaxf(sv[r][4], sv[r][5]), fmaxf(sv[r][6], sv[r][7])));
#pragma unroll
            for (int o = 8; o; o >>= 1) mx = fmaxf(mx, __shfl_xor_sync(0xffffffffu, mx, o));
            float mn = fmaxf(m[r], mx);
            fac[r] = exp2f(m[r] - mn);
            m[r] = mn;
            float rs = 0.f;
#pragma unroll
            for (int c = 0; c < 8; c++) {
                float p = exp2f(sv[r][c] - mn);
                sv[r][c] = p; rs += p;
            }
#pragma unroll
            for (int o = 8; o; o >>= 1) rs += __shfl_xor_sync(0xffffffffu, rs, o);
            l[r] = l[r] * fac[r] + rs;
        }
        // rescale O accumulators
#pragma unroll
        for (int i = 0; i < 4; i++) {
            unsigned long long f2 = pk2(fac[2 * i], fac[2 * i + 1]);
#pragma unroll
            for (int d = 0; d < 4; d++) mul2(acc2[i][d], f2);
        }

        // ---- write P (row-paired u64, plane-split over j pairs): conflict-free STS.128
#pragma unroll
        for (int i = 0; i < 4; i++) {
            unsigned long long* pw = psw + (4 * ty + i) * 128;
#pragma unroll
            for (int s = 0; s < 4; s++) {
                ulonglong2 w;
                w.x = pk2(sv[2 * i][2 * s],     sv[2 * i + 1][2 * s]);
                w.y = pk2(sv[2 * i][2 * s + 1], sv[2 * i + 1][2 * s + 1]);
                *(ulonglong2*)(pw + s * 32) = w;
            }
        }
        __syncthreads();

        // ---- O += P V : per jj: 4 broadcast LDS.64 (P pairs) + 2 LDS.128 (V dup)
        for (int jjb = 0; jjb < 128; jjb += 8) {
            const unsigned long long* vrow = vp + jjb * 64;
            int boff = (jjb >> 3) << 1;
#pragma unroll
            for (int u = 0; u < 8; u++) {
                int off = ((u >> 1) & 3) * 32 + boff + (u & 1);
                unsigned long long a0 = pp0[off];
                unsigned long long a1 = pp1[off];
                unsigned long long a2 = pp2[off];
                unsigned long long a3 = pp3[off];
                ulonglong2 v0 = *(const ulonglong2*)(vrow + u * 64);
                ulonglong2 v1 = *(const ulonglong2*)(vrow + u * 64 + 32);
                unsigned long long bz[4] = {v0.x, v0.y, v1.x, v1.y};
#pragma unroll
                for (int d = 0; d < 4; d++) {
                    fma2(acc2[0][d], a0, bz[d]);
                    fma2(acc2[1][d], a1, bz[d]);
                    fma2(acc2[2][d], a2, bz[d]);
                    fma2(acc2[3][d], a3, bz[d]);
                }
            }
        }
        __syncthreads();
    }

    // ---- epilogue: normalize, write [B,N,E]
    int n0 = qi * 128;
#pragma unroll
    for (int i = 0; i < 4; i++) {
        float inv0 = 1.f / l[2 * i], inv1 = 1.f / l[2 * i + 1];
        float2 t0 = u2f(acc2[i][0]), t1 = u2f(acc2[i][1]);
        float2 t2 = u2f(acc2[i][2]), t3 = u2f(acc2[i][3]);
        int r0 = n0 + 8 * ty + 2 * i;
        float4 o0 = make_float4(t0.x * inv0, t1.x * inv0, t2.x * inv0, t3.x * inv0);
        float4 o1 = make_float4(t0.y * inv1, t1.y * inv1, t2.y * inv1, t3.y * inv1);
        *(float4*)(g_att + ((size_t)(bb * Nc + r0)) * Ec + h * 64 + 4 * tx) = o0;
        *(float4*)(g_att + ((size_t)(bb * Nc + r0 + 1)) * Ec + h * 64 + 4 * tx) = o1;
    }
}

// ---------------------------------------------------------------------------
// Kernel 3: out = att @ W^T + bias. 128x128 tile, same f32x2 micro-kernel.
// ---------------------------------------------------------------------------
__global__ __launch_bounds__(256, 2) void proj_kernel(const float* __restrict__ W,
                                                      const float* __restrict__ bias,
                                                      float* __restrict__ out) {
    extern __shared__ char smc[];
    float* As = (float*)smc;                                        // [64][132]
    unsigned long long* Bdup = (unsigned long long*)(smc + 33792);  // [64][130]

    int m0 = blockIdx.x * 128, o0 = blockIdx.y * 128;
    int tid = threadIdx.x, tx = tid & 15, ty = tid >> 4;

    unsigned long long acc2[4][8];
#pragma unroll
    for (int i = 0; i < 4; i++)
#pragma unroll
        for (int c = 0; c < 8; c++) acc2[i][c] = 0ull;

    const float* ap = As + 8 * ty;
    const unsigned long long* bp = Bdup + 2 * tx;

    for (int kt = 0; kt < Ec / 64; kt++) {
#pragma unroll 4
        for (int it = 0; it < 32; it++) {
            int idx = it * 256 + tid;
            int r = idx >> 6, e = idx & 63;
            As[e * 132 + r] = g_att[(size_t)(m0 + r) * Ec + kt * 64 + e];
            Bdup[e * 130 + ((r >> 1) & 3) * 32 + ((r >> 3) << 1) + (r & 1)] =
                dup2(W[(size_t)(o0 + r) * Ec + kt * 64 + e]);
        }
        __syncthreads();

#pragma unroll 4
        for (int kk = 0; kk < 64; kk++) {
            ulonglong2 qa = *(const ulonglong2*)(ap + kk * 132);
            ulonglong2 qb = *(const ulonglong2*)(ap + kk * 132 + 4);
            const unsigned long long* kr = bp + kk * 130;
            ulonglong2 k0 = *(const ulonglong2*)(kr);
            ulonglong2 k1 = *(const ulonglong2*)(kr + 32);
            ulonglong2 k2 = *(const ulonglong2*)(kr + 64);
            ulonglong2 k3 = *(const ulonglong2*)(kr + 96);
            unsigned long long a0 = qa.x, a1 = qa.y, a2 = qb.x, a3 = qb.y;
            unsigned long long bz[8] = {k0.x, k0.y, k1.x, k1.y, k2.x, k2.y, k3.x, k3.y};
#pragma unroll
            for (int c = 0; c < 8; c++) {
                fma2(acc2[0][c], a0, bz[c]);
                fma2(acc2[1][c], a1, bz[c]);
                fma2(acc2[2][c], a2, bz[c]);
                fma2(acc2[3][c], a3, bz[c]);
            }
        }
        __syncthreads();
    }

    // epilogue + bias
#pragma unroll
    for (int i = 0; i < 4; i++) {
        int r0 = m0 + 8 * ty + 2 * i;
        float ov0[8], ov1[8];
#pragma unroll
        for (int c = 0; c < 8; c++) {
            float2 f = u2f(acc2[i][c]);
            float bv = bias[o0 + 8 * tx + c];
            ov0[c] = f.x + bv;
            ov1[c] = f.y + bv;
        }
        float* p0 = out + (size_t)r0 * Ec + o0 + 8 * tx;
        float* p1 = out + (size_t)(r0 + 1) * Ec + o0 + 8 * tx;
        *(float4*)(p0)     = make_float4(ov0[0], ov0[1], ov0[2], ov0[3]);
        *(float4*)(p0 + 4) = make_float4(ov0[4], ov0[5], ov0[6], ov0[7]);
        *(float4*)(p1)     = make_float4(ov1[0], ov1[1], ov1[2], ov1[3]);
        *(float4*)(p1 + 4) = make_float4(ov1[4], ov1[5], ov1[6], ov1[7]);
    }
}

// ---------------------------------------------------------------------------
extern "C" void kernel_launch(void* const* d_in, const int* in_sizes, int n_in,
                              void* d_out, int out_size) {
    const float* q  = (const float*)d_in[0];
    const float* k  = (const float*)d_in[1];
    const float* v  = (const float*)d_in[2];
    const float* qs = (const float*)d_in[3];
    const float* ks = (const float*)d_in[4];
    const float* pw = (const float*)d_in[5];
    const float* pb = (const float*)d_in[6];
    float* out = (float*)d_out;

    prep_kernel<<<(Bc * Nc * Hc) / 8, 256>>>(q, k, v, qs, ks);

    int smemA = 33792 + 66560 + 65536 + 65536;   // 231424 B
    cudaFuncSetAttribute(attn_kernel, cudaFuncAttributeMaxDynamicSharedMemorySize, smemA);
    attn_kernel<<<dim3(Nc / 128, Bc * Hc), 256, smemA>>>();

    int smemP = 33792 + 66560;                    // 100352 B
    cudaFuncSetAttribute(proj_kernel, cudaFuncAttributeMaxDynamicSharedMemorySize, smemP);
    proj_kernel<<<dim3((Bc * Nc) / 128, Ec / 128), 256, smemP>>>(pw, pb, out);
}

// round 10
// speedup vs baseline: 1.0001x; 1.0001x over previous
#include <cuda_runtime.h>
#include <math.h>

namespace {
constexpr int Bc = 4, Nc = 2048, Ec = 768, Hc = 12, Dc = 64;
}

// Scratch (allocation-free rule: __device__ globals)
__device__ float g_qh[(size_t)Bc * Hc * Nc * Dc];
__device__ float g_kh[(size_t)Bc * Hc * Nc * Dc];
__device__ float g_vh[(size_t)Bc * Hc * Nc * Dc];
__device__ float g_att[(size_t)Bc * Nc * Ec];

// ---------------- f32x2 helpers (packed fp32 pair in u64) ----------------
__device__ __forceinline__ void fma2(unsigned long long& d,
                                     unsigned long long a, unsigned long long b) {
    asm("fma.rn.f32x2 %0, %1, %2, %0;" : "+l"(d) : "l"(a), "l"(b));
}
__device__ __forceinline__ void mul2(unsigned long long& d, unsigned long long b) {
    asm("mul.rn.f32x2 %0, %0, %1;" : "+l"(d) : "l"(b));
}
__device__ __forceinline__ unsigned long long pk2(float lo, float hi) {
    unsigned long long r;
    asm("mov.b64 %0, {%1, %2};" : "=l"(r) : "f"(lo), "f"(hi));
    return r;
}
__device__ __forceinline__ unsigned long long dup2(float x) {
    unsigned int u = __float_as_uint(x);
    return ((unsigned long long)u << 32) | (unsigned long long)u;
}
__device__ __forceinline__ float2 u2f(unsigned long long v) {
    float2 r;
    r.x = __uint_as_float((unsigned int)v);
    r.y = __uint_as_float((unsigned int)(v >> 32));
    return r;
}

// ---------------------------------------------------------------------------
// Kernel 1: RMSNorm + xPos RoPE + head-split transpose. One warp per (b,n,h).
// Folds (1/sqrt(D)) * log2(e) into Q so softmax can use exp2f.
// ---------------------------------------------------------------------------
__global__ void prep_kernel(const float* __restrict__ q, const float* __restrict__ k,
                            const float* __restrict__ v,
                            const float* __restrict__ qs, const float* __restrict__ ks) {
    int w = (blockIdx.x * blockDim.x + threadIdx.x) >> 5;
    int lane = threadIdx.x & 31;
    if (w >= Bc * Nc * Hc) return;
    int h = w % Hc;
    int bn = w / Hc;
    int n = bn % Nc;
    int b = bn / Nc;

    size_t in_off = (size_t)bn * Ec + h * Dc;
    int d0 = lane, d1 = lane + 32;

    float q0 = q[in_off + d0], q1 = q[in_off + d1];
    float k0 = k[in_off + d0], k1 = k[in_off + d1];
    float v0 = v[in_off + d0], v1 = v[in_off + d1];

    float sq = q0 * q0 + q1 * q1;
    float sk = k0 * k0 + k1 * k1;
#pragma unroll
    for (int o = 16; o; o >>= 1) {
        sq += __shfl_xor_sync(0xffffffffu, sq, o);
        sk += __shfl_xor_sync(0xffffffffu, sk, o);
    }
    float qn = rsqrtf(sq * (1.0f / 64.0f) + 1e-6f);
    float kn = rsqrtf(sk * (1.0f / 64.0f) + 1e-6f);
    q0 *= qs[d0] * qn; q1 *= qs[d1] * qn;
    k0 *= ks[d0] * kn; k1 *= ks[d1] * kn;

    // xPos RoPE on dims [0,32)
    int p = d0 >> 1;
    double invf = pow(10000.0, -(double)p / 16.0);
    double fr = (double)n * invf;
    float c = (float)cos(fr), s = (float)sin(fr);
    double base = (2.0 * p + 12.8) / 44.8;
    double pw = ((double)n - 1024.0) / 512.0;
    float sc = (float)pow(base, pw);

    float qp_ = __shfl_xor_sync(0xffffffffu, q0, 1);
    float kp_ = __shfl_xor_sync(0xffffffffu, k0, 1);
    float sgn = (d0 & 1) ? s : -s;
    q0 = (q0 * c + qp_ * sgn) * sc;
    k0 = (k0 * c + kp_ * sgn) / sc;

    // fold softmax scale 1/sqrt(64) AND log2(e) into Q (exp2 softmax)
    const float QSCL = 0.125f * 1.4426950408889634f;
    q0 *= QSCL; q1 *= QSCL;

    size_t out_off = (((size_t)(b * Hc + h)) * Nc + n) * Dc;
    g_qh[out_off + d0] = q0; g_qh[out_off + d1] = q1;
    g_kh[out_off + d0] = k0; g_kh[out_off + d1] = k1;
    g_vh[out_off + d0] = v0; g_vh[out_off + d1] = v1;
}

// ---------------------------------------------------------------------------
// Kernel 2: causal flash attention, fp32x2 packed FMA.
// Block = 256 thr (16x16), block tile 128x128, micro tile 8x8 (row-paired).
// SMEM layouts (all hot accesses are 16B*tx conflict-free):
//   Qd   [64 d][132 rows]       floats, row-pairs read as ulonglong2 (broadcast)
//   Kdup [64 d][130]            u64 dup'd K values, plane-split over col pairs
//   Vdup [128 j][64]            u64 dup'd V values, plane-split over d pairs
//   Ps2  [64 rowpair][128 j]    u64 row-paired P, plane-split over j pairs
// ---------------------------------------------------------------------------
__global__ __launch_bounds__(256, 1) void attn_kernel() {
    extern __shared__ char smc[];
    float* Qd = (float*)smc;                                          // 33792 B
    unsigned long long* Kdup = (unsigned long long*)(smc + 33792);    // 66560 B
    unsigned long long* Vdup = Kdup + 64 * 130;                       // 65536 B
    unsigned long long* Ps2  = Vdup + 128 * 64;                       // 65536 B

    int qi = (int)gridDim.x - 1 - (int)blockIdx.x;   // big tiles first
    int bh = blockIdx.y;
    int bb = bh / Hc, h = bh % Hc;
    int tid = threadIdx.x;
    int tx = tid & 15, ty = tid >> 4;

    size_t base = (size_t)bh * Nc * Dc;
    const float* Qg = g_qh + base + (size_t)qi * 128 * Dc;

    // load Q tile (once), d-major transpose; stride 132 breaks store conflicts
#pragma unroll 8
    for (int it = 0; it < 32; it++) {
        int idx = it * 256 + tid;
        int row = idx >> 6, d = idx & 63;
        Qd[d * 132 + row] = Qg[row * 64 + d];
    }

    float m[8], l[8];
    unsigned long long acc2[4][4];   // O acc: [rowpair][d], rows (8ty+2i, 8ty+2i+1)
#pragma unroll
    for (int r = 0; r < 8; r++) { m[r] = -INFINITY; l[r] = 0.f; }
#pragma unroll
    for (int i = 0; i < 4; i++)
#pragma unroll
        for (int d = 0; d < 4; d++) acc2[i][d] = 0ull;

    const float* qp = Qd + 8 * ty;
    const unsigned long long* kp = Kdup + 2 * tx;
    const unsigned long long* pp0 = Ps2 + (4 * ty + 0) * 128;
    const unsigned long long* pp1 = Ps2 + (4 * ty + 1) * 128;
    const unsigned long long* pp2 = Ps2 + (4 * ty + 2) * 128;
    const unsigned long long* pp3 = Ps2 + (4 * ty + 3) * 128;
    const unsigned long long* vp = Vdup + 2 * tx;
    unsigned long long* psw = Ps2 + 2 * tx;   // write base, + (4ty+i)*128 + s*32

    for (int kt = 0; kt <= qi; kt++) {
        const float* Kg = g_kh + base + (size_t)kt * 128 * Dc;
        const float* Vg = g_vh + base + (size_t)kt * 128 * Dc;
        // fill K (dup'd, plane-split over col pairs) and V (dup'd, plane-split over d pairs)
#pragma unroll 4
        for (int it = 0; it < 32; it++) {
            int idx = it * 256 + tid;
            int j = idx >> 6, d = idx & 63;
            float kv = Kg[j * 64 + d];
            float vv = Vg[j * 64 + d];
            Kdup[d * 130 + ((j >> 1) & 3) * 32 + ((j >> 3) << 1) + (j & 1)] = dup2(kv);
            Vdup[j * 64 + ((d >> 1) & 1) * 32 + ((d >> 2) << 1) + (d & 1)] = dup2(vv);
        }
        __syncthreads();

        // ---- S = Q K^T : acc s2[rowpair i][col c], rows (2i,2i+1)+8ty, col 8tx+c
        unsigned long long s2[4][8];
#pragma unroll
        for (int i = 0; i < 4; i++)
#pragma unroll
            for (int c = 0; c < 8; c++) s2[i][c] = 0ull;

#pragma unroll 4
        for (int kk = 0; kk < 64; kk++) {
            ulonglong2 qa = *(const ulonglong2*)(qp + kk * 132);
            ulonglong2 qb = *(const ulonglong2*)(qp + kk * 132 + 4);
            const unsigned long long* kr = kp + kk * 130;
            ulonglong2 k0 = *(const ulonglong2*)(kr);
            ulonglong2 k1 = *(const ulonglong2*)(kr + 32);
            ulonglong2 k2 = *(const ulonglong2*)(kr + 64);
            ulonglong2 k3 = *(const ulonglong2*)(kr + 96);
            unsigned long long a0 = qa.x, a1 = qa.y, a2 = qb.x, a3 = qb.y;
            unsigned long long bz[8] = {k0.x, k0.y, k1.x, k1.y, k2.x, k2.y, k3.x, k3.y};
#pragma unroll
            for (int c = 0; c < 8; c++) {
                fma2(s2[0][c], a0, bz[c]);
                fma2(s2[1][c], a1, bz[c]);
                fma2(s2[2][c], a2, bz[c]);
                fma2(s2[3][c], a3, bz[c]);
            }
        }

        // ---- unpack scores
        float sv[8][8];
#pragma unroll
        for (int i = 0; i < 4; i++)
#pragma unroll
            for (int c = 0; c < 8; c++) {
                float2 f = u2f(s2[i][c]);
                sv[2 * i][c] = f.x;
                sv[2 * i + 1][c] = f.y;
            }

        if (kt == qi) {   // causal mask on diagonal tile
            int rb = 8 * ty, cb = 8 * tx;
#pragma unroll
            for (int r = 0; r < 8; r++)
#pragma unroll
                for (int c = 0; c < 8; c++)
                    if (cb + c > rb + r) sv[r][c] = -INFINITY;
        }

        // ---- online softmax (base-2; log2e folded into Q)
        float fac[8];
#pragma unroll
        for (int r = 0; r < 8; r++) {
            float mx = fmaxf(fmaxf(fmaxf(sv[r][0], sv[r][1]), fmaxf(sv[r][2], sv[r][3])),
                             fmaxf(fmaxf(sv[r][4], sv[r][5]), fmaxf(sv[r][6], sv[r][7])));
#pragma unroll
            for (int o = 8; o; o >>= 1) mx = fmaxf(mx, __shfl_xor_sync(0xffffffffu, mx, o));
            float mn = fmaxf(m[r], mx);
            fac[r] = exp2f(m[r] - mn);
            m[r] = mn;
            float rs = 0.f;
#pragma unroll
            for (int c = 0; c < 8; c++) {
                float p = exp2f(sv[r][c] - mn);
                sv[r][c] = p; rs += p;
            }
#pragma unroll
            for (int o = 8; o; o >>= 1) rs += __shfl_xor_sync(0xffffffffu, rs, o);
            l[r] = l[r] * fac[r] + rs;
        }
        // rescale O accumulators
#pragma unroll
        for (int i = 0; i < 4; i++) {
            unsigned long long f2 = pk2(fac[2 * i], fac[2 * i + 1]);
#pragma unroll
            for (int d = 0; d < 4; d++) mul2(acc2[i][d], f2);
        }

        // ---- write P (row-paired u64, plane-split over j pairs): conflict-free STS.128
#pragma unroll
        for (int i = 0; i < 4; i++) {
            unsigned long long* pw = psw + (4 * ty + i) * 128;
#pragma unroll
            for (int s = 0; s < 4; s++) {
                ulonglong2 w;
                w.x = pk2(sv[2 * i][2 * s],     sv[2 * i + 1][2 * s]);
                w.y = pk2(sv[2 * i][2 * s + 1], sv[2 * i + 1][2 * s + 1]);
                *(ulonglong2*)(pw + s * 32) = w;
            }
        }
        __syncthreads();

        // ---- O += P V : per jj: 4 broadcast LDS.64 (P pairs) + 2 LDS.128 (V dup)
        for (int jjb = 0; jjb < 128; jjb += 8) {
            const unsigned long long* vrow = vp + jjb * 64;
            int boff = (jjb >> 3) << 1;
#pragma unroll
            for (int u = 0; u < 8; u++) {
                int off = ((u >> 1) & 3) * 32 + boff + (u & 1);
                unsigned long long a0 = pp0[off];
                unsigned long long a1 = pp1[off];
                unsigned long long a2 = pp2[off];
                unsigned long long a3 = pp3[off];
                ulonglong2 v0 = *(const ulonglong2*)(vrow + u * 64);
                ulonglong2 v1 = *(const ulonglong2*)(vrow + u * 64 + 32);
                unsigned long long bz[4] = {v0.x, v0.y, v1.x, v1.y};
#pragma unroll
                for (int d = 0; d < 4; d++) {
                    fma2(acc2[0][d], a0, bz[d]);
                    fma2(acc2[1][d], a1, bz[d]);
                    fma2(acc2[2][d], a2, bz[d]);
                    fma2(acc2[3][d], a3, bz[d]);
                }
            }
        }
        __syncthreads();
    }

    // ---- epilogue: normalize, write [B,N,E]
    int n0 = qi * 128;
#pragma unroll
    for (int i = 0; i < 4; i++) {
        float inv0 = 1.f / l[2 * i], inv1 = 1.f / l[2 * i + 1];
        float2 t0 = u2f(acc2[i][0]), t1 = u2f(acc2[i][1]);
        float2 t2 = u2f(acc2[i][2]), t3 = u2f(acc2[i][3]);
        int r0 = n0 + 8 * ty + 2 * i;
        float4 o0 = make_float4(t0.x * inv0, t1.x * inv0, t2.x * inv0, t3.x * inv0);
        float4 o1 = make_float4(t0.y * inv1, t1.y * inv1, t2.y * inv1, t3.y * inv1);
        *(float4*)(g_att + ((size_t)(bb * Nc + r0)) * Ec + h * 64 + 4 * tx) = o0;
        *(float4*)(g_att + ((size_t)(bb * Nc + r0 + 1)) * Ec + h * 64 + 4 * tx) = o1;
    }
}

// ---------------------------------------------------------------------------
// Kernel 3: out = att @ W^T + bias. 128x128 tile, same f32x2 micro-kernel.
// ---------------------------------------------------------------------------
__global__ __launch_bounds__(256, 2) void proj_kernel(const float* __restrict__ W,
                                                      const float* __restrict__ bias,
                                                      float* __restrict__ out) {
    extern __shared__ char smc[];
    float* As = (float*)smc;                                        // [64][132]
    unsigned long long* Bdup = (unsigned long long*)(smc + 33792);  // [64][130]

    int m0 = blockIdx.x * 128, o0 = blockIdx.y * 128;
    int tid = threadIdx.x, tx = tid & 15, ty = tid >> 4;

    unsigned long long acc2[4][8];
#pragma unroll
    for (int i = 0; i < 4; i++)
#pragma unroll
        for (int c = 0; c < 8; c++) acc2[i][c] = 0ull;

    const float* ap = As + 8 * ty;
    const unsigned long long* bp = Bdup + 2 * tx;

    for (int kt = 0; kt < Ec / 64; kt++) {
#pragma unroll 4
        for (int it = 0; it < 32; it++) {
            int idx = it * 256 + tid;
            int r = idx >> 6, e = idx & 63;
            As[e * 132 + r] = g_att[(size_t)(m0 + r) * Ec + kt * 64 + e];
            Bdup[e * 130 + ((r >> 1) & 3) * 32 + ((r >> 3) << 1) + (r & 1)] =
                dup2(W[(size_t)(o0 + r) * Ec + kt * 64 + e]);
        }
        __syncthreads();

#pragma unroll 4
        for (int kk = 0; kk < 64; kk++) {
            ulonglong2 qa = *(const ulonglong2*)(ap + kk * 132);
            ulonglong2 qb = *(const ulonglong2*)(ap + kk * 132 + 4);
            const unsigned long long* kr = bp + kk * 130;
            ulonglong2 k0 = *(const ulonglong2*)(kr);
            ulonglong2 k1 = *(const ulonglong2*)(kr + 32);
            ulonglong2 k2 = *(const ulonglong2*)(kr + 64);
            ulonglong2 k3 = *(const ulonglong2*)(kr + 96);
            unsigned long long a0 = qa.x, a1 = qa.y, a2 = qb.x, a3 = qb.y;
            unsigned long long bz[8] = {k0.x, k0.y, k1.x, k1.y, k2.x, k2.y, k3.x, k3.y};
#pragma unroll
            for (int c = 0; c < 8; c++) {
                fma2(acc2[0][c], a0, bz[c]);
                fma2(acc2[1][c], a1, bz[c]);
                fma2(acc2[2][c], a2, bz[c]);
                fma2(acc2[3][c], a3, bz[c]);
            }
        }
        __syncthreads();
    }

    // epilogue + bias
#pragma unroll
    for (int i = 0; i < 4; i++) {
        int r0 = m0 + 8 * ty + 2 * i;
        float ov0[8], ov1[8];
#pragma unroll
        for (int c = 0; c < 8; c++) {
            float2 f = u2f(acc2[i][c]);
            float bv = bias[o0 + 8 * tx + c];
            ov0[c] = f.x + bv;
            ov1[c] = f.y + bv;
        }
        float* p0 = out + (size_t)r0 * Ec + o0 + 8 * tx;
        float* p1 = out + (size_t)(r0 + 1) * Ec + o0 + 8 * tx;
        *(float4*)(p0)     = make_float4(ov0[0], ov0[1], ov0[2], ov0[3]);
        *(float4*)(p0 + 4) = make_float4(ov0[4], ov0[5], ov0[6], ov0[7]);
        *(float4*)(p1)     = make_float4(ov1[0], ov1[1], ov1[2], ov1[3]);
        *(float4*)(p1 + 4) = make_float4(ov1[4], ov1[5], ov1[6], ov1[7]);
    }
}

// ---------------------------------------------------------------------------
extern "C" void kernel_launch(void* const* d_in, const int* in_sizes, int n_in,
                              void* d_out, int out_size) {
    const float* q  = (const float*)d_in[0];
    const float* k  = (const float*)d_in[1];
    const float* v  = (const float*)d_in[2];
    const float* qs = (const float*)d_in[3];
    const float* ks = (const float*)d_in[4];
    const float* pw = (const float*)d_in[5];
    const float* pb = (const float*)d_in[6];
    float* out = (float*)d_out;

    prep_kernel<<<(Bc * Nc * Hc) / 8, 256>>>(q, k, v, qs, ks);

    int smemA = 33792 + 66560 + 65536 + 65536;   // 231424 B
    cudaFuncSetAttribute(attn_kernel, cudaFuncAttributeMaxDynamicSharedMemorySize, smemA);
    attn_kernel<<<dim3(Nc / 128, Bc * Hc), 256, smemA>>>();

    int smemP = 33792 + 66560;                    // 100352 B
    cudaFuncSetAttribute(proj_kernel, cudaFuncAttributeMaxDynamicSharedMemorySize, smemP);
    proj_kernel<<<dim3((Bc * Nc) / 128, Ec / 128), 256, smemP>>>(pw, pb, out);
}

// round 16
// speedup vs baseline: 1.5025x; 1.5023x over previous
#include <cuda_runtime.h>
#include <cuda_bf16.h>
#include <math.h>
#include <stdint.h>

namespace {
constexpr int Bc = 4, Nc = 2048, Ec = 768, Hc = 12, Dc = 64;
constexpr int BHc = Bc * Hc;  // 48
}

// Scratch (allocation-free rule: __device__ globals)
__device__ __align__(256) __nv_bfloat16 g_q_hi[(size_t)BHc * Nc * Dc];
__device__ __align__(256) __nv_bfloat16 g_q_lo[(size_t)BHc * Nc * Dc];
__device__ __align__(256) __nv_bfloat16 g_k_hi[(size_t)BHc * Nc * Dc];
__device__ __align__(256) __nv_bfloat16 g_k_lo[(size_t)BHc * Nc * Dc];
__device__ __align__(256) __nv_bfloat16 g_v_hi[(size_t)BHc * Nc * Dc];
__device__ __align__(256) __nv_bfloat16 g_v_lo[(size_t)BHc * Nc * Dc];
__device__ __align__(256) __nv_bfloat16 g_a_hi[(size_t)Bc * Nc * Ec];
__device__ __align__(256) __nv_bfloat16 g_a_lo[(size_t)Bc * Nc * Ec];
__device__ __align__(256) __nv_bfloat16 g_w_hi[(size_t)Ec * Ec];
__device__ __align__(256) __nv_bfloat16 g_w_lo[(size_t)Ec * Ec];

// ---------------- helpers ----------------
__device__ __forceinline__ uint32_t smem_u32(const void* p) {
    uint32_t a;
    asm("{ .reg .u64 t; cvta.to.shared.u64 t, %1; cvt.u32.u64 %0, t; }" : "=r"(a) : "l"(p));
    return a;
}
__device__ __forceinline__ float ex2(float x) {
    float r; asm("ex2.approx.ftz.f32 %0, %1;" : "=f"(r) : "f"(x)); return r;
}
// pack (lo,hi) floats into bf16x2: lo -> bits[0:16), hi -> bits[16:32)
__device__ __forceinline__ uint32_t bf16x2_of(float lo, float hi) {
    uint32_t r;
    asm("cvt.rn.bf16x2.f32 %0, %1, %2;" : "=r"(r) : "f"(hi), "f"(lo));
    return r;
}
__device__ __forceinline__ float lo16f(uint32_t h) { return __uint_as_float(h << 16); }
__device__ __forceinline__ float hi16f(uint32_t h) { return __uint_as_float(h & 0xffff0000u); }

__device__ __forceinline__ void ldsm4(uint32_t* r, uint32_t a) {
    asm volatile("ldmatrix.sync.aligned.m8n8.x4.shared.b16 {%0,%1,%2,%3}, [%4];"
                 : "=r"(r[0]), "=r"(r[1]), "=r"(r[2]), "=r"(r[3]) : "r"(a));
}
__device__ __forceinline__ void ldsm4t(uint32_t* r, uint32_t a) {
    asm volatile("ldmatrix.sync.aligned.m8n8.x4.trans.shared.b16 {%0,%1,%2,%3}, [%4];"
                 : "=r"(r[0]), "=r"(r[1]), "=r"(r[2]), "=r"(r[3]) : "r"(a));
}
__device__ __forceinline__ void mma_bf16(float* d, const uint32_t* a, const uint32_t* b) {
    asm volatile("mma.sync.aligned.m16n8k16.row.col.f32.bf16.bf16.f32 "
                 "{%0,%1,%2,%3}, {%4,%5,%6,%7}, {%8,%9}, {%0,%1,%2,%3};"
                 : "+f"(d[0]), "+f"(d[1]), "+f"(d[2]), "+f"(d[3])
                 : "r"(a[0]), "r"(a[1]), "r"(a[2]), "r"(a[3]), "r"(b[0]), "r"(b[1]));
}

// swizzled byte offsets: 64-col bf16 tile (128B rows) and 128-col (256B rows)
__device__ __forceinline__ int sw64(int row, int col) {
    return row * 128 + ((((col >> 3) ^ row) & 7) << 4) + ((col & 7) << 1);
}
__device__ __forceinline__ int sw128(int row, int col) {
    int c = col >> 3;
    return row * 256 + (((c & 8) | ((c ^ row) & 7)) << 4) + ((col & 7) << 1);
}

// 128 rows x 64 bf16 (128B rows) into swizzled smem; coalesced + conflict-free
__device__ __forceinline__ void copy_rows(char* dst, const __nv_bfloat16* src,
                                          int stride, int tid) {
#pragma unroll
    for (int it = 0; it < 4; it++) {
        int u = it * 256 + tid;
        int r = u >> 3, c = u & 7;
        uint4 x = *(const uint4*)(src + (size_t)r * stride + c * 8);
        *(uint4*)(dst + r * 128 + (((c ^ r) & 7) << 4)) = x;
    }
}

// ---------------------------------------------------------------------------
// K1: RMSNorm + xPos RoPE; bf16 hi/lo split for q,k,v; layout [bh][n][d].
// Folds (1/sqrt(D)) * log2(e) into Q (exp2 softmax).
// ---------------------------------------------------------------------------
__global__ void prep_kernel(const float* __restrict__ q, const float* __restrict__ k,
                            const float* __restrict__ v,
                            const float* __restrict__ qs, const float* __restrict__ ks) {
    int w = (blockIdx.x * blockDim.x + threadIdx.x) >> 5;
    int lane = threadIdx.x & 31;
    if (w >= Bc * Nc * Hc) return;
    int h = w % Hc, bn = w / Hc, n = bn % Nc, b = bn / Nc;
    size_t in_off = (size_t)bn * Ec + h * Dc;
    int d0 = lane, d1 = lane + 32;

    float q0 = q[in_off + d0], q1 = q[in_off + d1];
    float k0 = k[in_off + d0], k1 = k[in_off + d1];
    float v0 = v[in_off + d0], v1 = v[in_off + d1];

    float sq = q0 * q0 + q1 * q1, sk = k0 * k0 + k1 * k1;
#pragma unroll
    for (int o = 16; o; o >>= 1) {
        sq += __shfl_xor_sync(0xffffffffu, sq, o);
        sk += __shfl_xor_sync(0xffffffffu, sk, o);
    }
    float qn = rsqrtf(sq * (1.0f / 64.0f) + 1e-6f);
    float kn = rsqrtf(sk * (1.0f / 64.0f) + 1e-6f);
    q0 *= qs[d0] * qn; q1 *= qs[d1] * qn;
    k0 *= ks[d0] * kn; k1 *= ks[d1] * kn;

    int p = d0 >> 1;
    double invf = pow(10000.0, -(double)p / 16.0);
    double fr = (double)n * invf;
    float c = (float)cos(fr), s = (float)sin(fr);
    float sc = (float)pow((2.0 * p + 12.8) / 44.8, ((double)n - 1024.0) / 512.0);
    float qp_ = __shfl_xor_sync(0xffffffffu, q0, 1);
    float kp_ = __shfl_xor_sync(0xffffffffu, k0, 1);
    float sgn = (d0 & 1) ? s : -s;
    q0 = (q0 * c + qp_ * sgn) * sc;
    k0 = (k0 * c + kp_ * sgn) / sc;

    const float QSCL = 0.125f * 1.4426950408889634f;
    q0 *= QSCL; q1 *= QSCL;

    size_t oo = (((size_t)(b * Hc + h)) * Nc + n) * Dc;
    __nv_bfloat16 a;
    a = __float2bfloat16(q0); g_q_hi[oo + d0] = a; g_q_lo[oo + d0] = __float2bfloat16(q0 - __bfloat162float(a));
    a = __float2bfloat16(q1); g_q_hi[oo + d1] = a; g_q_lo[oo + d1] = __float2bfloat16(q1 - __bfloat162float(a));
    a = __float2bfloat16(k0); g_k_hi[oo + d0] = a; g_k_lo[oo + d0] = __float2bfloat16(k0 - __bfloat162float(a));
    a = __float2bfloat16(k1); g_k_hi[oo + d1] = a; g_k_lo[oo + d1] = __float2bfloat16(k1 - __bfloat162float(a));
    a = __float2bfloat16(v0); g_v_hi[oo + d0] = a; g_v_lo[oo + d0] = __float2bfloat16(v0 - __bfloat162float(a));
    a = __float2bfloat16(v1); g_v_hi[oo + d1] = a; g_v_lo[oo + d1] = __float2bfloat16(v1 - __bfloat162float(a));
}

// K1b: W bf16 hi/lo split
__global__ void wprep_kernel(const float* __restrict__ w) {
    int idx = blockIdx.x * blockDim.x + threadIdx.x;
    if (idx >= Ec * Ec / 2) return;
    float x0 = w[2 * idx], x1 = w[2 * idx + 1];
    uint32_t h2 = bf16x2_of(x0, x1);
    ((uint32_t*)g_w_hi)[idx] = h2;
    ((uint32_t*)g_w_lo)[idx] = bf16x2_of(x0 - lo16f(h2), x1 - hi16f(h2));
}

// ---------------------------------------------------------------------------
// K2: causal flash attention via mma.sync bf16 split-precision.
// 128x128 tiles, 8 warps (16 rows each). No-max exp2 softmax; O accumulates
// in registers across kt; l reduced once at the end.
// ---------------------------------------------------------------------------
__global__ __launch_bounds__(256, 1) void attn_kernel() {
    extern __shared__ char sm[];
    enum { QHI = 0, QLO = 16384, KHI = 32768, KLO = 49152,
           VHI = 65536, VLO = 81920, PHI = 98304, PLO = 131072 };  // 160KB
    const int tid = threadIdx.x, w = tid >> 5, lane = tid & 31;
    const uint32_t smb = smem_u32(sm);
    const int qi = 15 - (int)blockIdx.x;          // big tiles first
    const int bh = blockIdx.y;
    const size_t hb = (size_t)bh * Nc * Dc;
    const int r0 = w * 16;

    // ldmatrix per-lane addressing offsets
    const int a_r = (lane & 7) + ((lane & 8) ? 8 : 0);   // A / Vt row group
    const int a_c = (lane & 16) ? 8 : 0;                  // A / Vt col group
    const int b_r = (lane & 7) + ((lane & 16) ? 8 : 0);  // B (K) row group
    const int b_c = (lane & 8) ? 8 : 0;                   // B (K) col group

    copy_rows(sm + QHI, g_q_hi + hb + (size_t)qi * 128 * Dc, Dc, tid);
    copy_rows(sm + QLO, g_q_lo + hb + (size_t)qi * 128 * Dc, Dc, tid);

    float O[8][4];
#pragma unroll
    for (int i = 0; i < 8; i++)
#pragma unroll
        for (int e = 0; e < 4; e++) O[i][e] = 0.f;
    float lr0 = 0.f, lr1 = 0.f;

    const int rl0 = r0 + (lane >> 2), rl1 = r0 + (lane >> 2) + 8;
    const int c0 = 2 * (lane & 3);

    for (int kt = 0; kt <= qi; kt++) {
        __syncthreads();   // protect K/V overwrite vs previous iter's reads
        copy_rows(sm + KHI, g_k_hi + hb + (size_t)kt * 128 * Dc, Dc, tid);
        copy_rows(sm + KLO, g_k_lo + hb + (size_t)kt * 128 * Dc, Dc, tid);
        copy_rows(sm + VHI, g_v_hi + hb + (size_t)kt * 128 * Dc, Dc, tid);
        copy_rows(sm + VLO, g_v_lo + hb + (size_t)kt * 128 * Dc, Dc, tid);
        __syncthreads();

        // ---- S = Q K^T (16x128 per warp), 3-term split
        float S[16][4];
#pragma unroll
        for (int i = 0; i < 16; i++)
#pragma unroll
            for (int e = 0; e < 4; e++) S[i][e] = 0.f;

#pragma unroll
        for (int ks = 0; ks < 4; ks++) {
            int k0 = ks * 16;
            uint32_t ah[4], al[4];
            ldsm4(ah, smb + QHI + sw64(r0 + a_r, k0 + a_c));
            ldsm4(al, smb + QLO + sw64(r0 + a_r, k0 + a_c));
#pragma unroll
            for (int nb2 = 0; nb2 < 8; nb2++) {
                int n0 = nb2 * 16;
                uint32_t kh_[4], kl_[4];
                ldsm4(kh_, smb + KHI + sw64(n0 + b_r, k0 + b_c));
                ldsm4(kl_, smb + KLO + sw64(n0 + b_r, k0 + b_c));
                mma_bf16(S[2 * nb2],     ah, kh_);
                mma_bf16(S[2 * nb2],     al, kh_);
                mma_bf16(S[2 * nb2],     ah, kl_);
                mma_bf16(S[2 * nb2 + 1], ah, kh_ + 2);
                mma_bf16(S[2 * nb2 + 1], al, kh_ + 2);
                mma_bf16(S[2 * nb2 + 1], ah, kl_ + 2);
            }
        }

        // ---- exp2 softmax (no max), mask diag, split P to bf16 hi/lo in smem
        const bool diag = (kt == qi);
#pragma unroll
        for (int nb = 0; nb < 16; nb++) {
            int cg = nb * 8 + c0;
            float p00 = ex2(S[nb][0]);
            float p01 = ex2(S[nb][1]);
            float p10 = ex2(S[nb][2]);
            float p11 = ex2(S[nb][3]);
            if (diag) {
                if (cg     > rl0) p00 = 0.f;
                if (cg + 1 > rl0) p01 = 0.f;
                if (cg     > rl1) p10 = 0.f;
                if (cg + 1 > rl1) p11 = 0.f;
            }
            lr0 += p00 + p01;
            lr1 += p10 + p11;
            uint32_t h0 = bf16x2_of(p00, p01);
            uint32_t l0 = bf16x2_of(p00 - lo16f(h0), p01 - hi16f(h0));
            uint32_t h1 = bf16x2_of(p10, p11);
            uint32_t l1 = bf16x2_of(p10 - lo16f(h1), p11 - hi16f(h1));
            *(uint32_t*)(sm + PHI + sw128(rl0, cg)) = h0;
            *(uint32_t*)(sm + PLO + sw128(rl0, cg)) = l0;
            *(uint32_t*)(sm + PHI + sw128(rl1, cg)) = h1;
            *(uint32_t*)(sm + PLO + sw128(rl1, cg)) = l1;
        }
        __syncwarp();   // P rows are warp-private; order stores vs ldmatrix

        // ---- O += P V (16x64 per warp), 3-term split, V^T via ldmatrix.trans
#pragma unroll
        for (int ks = 0; ks < 8; ks++) {
            int j0 = ks * 16;
            uint32_t ph[4], pl[4];
            ldsm4(ph, smb + PHI + sw128(r0 + a_r, j0 + a_c));
            ldsm4(pl, smb + PLO + sw128(r0 + a_r, j0 + a_c));
#pragma unroll
            for (int db2 = 0; db2 < 4; db2++) {   // FIXED: full D=64 (was < 2)
                int d0 = db2 * 16;
                uint32_t vh_[4], vl_[4];
                ldsm4t(vh_, smb + VHI + sw64(j0 + a_r, d0 + a_c));
                ldsm4t(vl_, smb + VLO + sw64(j0 + a_r, d0 + a_c));
                mma_bf16(O[2 * db2],     ph, vh_);
                mma_bf16(O[2 * db2],     pl, vh_);
                mma_bf16(O[2 * db2],     ph, vl_);
                mma_bf16(O[2 * db2 + 1], ph, vh_ + 2);
                mma_bf16(O[2 * db2 + 1], pl, vh_ + 2);
                mma_bf16(O[2 * db2 + 1], ph, vl_ + 2);
            }
        }
    }

    // ---- finalize l (butterfly within quad) and write bf16 hi/lo output
    lr0 += __shfl_xor_sync(0xffffffffu, lr0, 1);
    lr0 += __shfl_xor_sync(0xffffffffu, lr0, 2);
    lr1 += __shfl_xor_sync(0xffffffffu, lr1, 1);
    lr1 += __shfl_xor_sync(0xffffffffu, lr1, 2);
    float inv0 = 1.f / lr0, inv1 = 1.f / lr1;

    const int bb = bh / Hc, hh = bh % Hc;
    const int rg0 = qi * 128 + rl0;
#pragma unroll
    for (int nb = 0; nb < 8; nb++) {
        int dg = hh * 64 + nb * 8 + c0;
        float y00 = O[nb][0] * inv0, y01 = O[nb][1] * inv0;
        float y10 = O[nb][2] * inv1, y11 = O[nb][3] * inv1;
        uint32_t h0 = bf16x2_of(y00, y01);
        uint32_t l0 = bf16x2_of(y00 - lo16f(h0), y01 - hi16f(h0));
        uint32_t h1 = bf16x2_of(y10, y11);
        uint32_t l1 = bf16x2_of(y10 - lo16f(h1), y11 - hi16f(h1));
        size_t off0 = (size_t)(bb * Nc + rg0) * Ec + dg;
        size_t off1 = (size_t)(bb * Nc + rg0 + 8) * Ec + dg;
        *(uint32_t*)(g_a_hi + off0) = h0;
        *(uint32_t*)(g_a_lo + off0) = l0;
        *(uint32_t*)(g_a_hi + off1) = h1;
        *(uint32_t*)(g_a_lo + off1) = l1;
    }
}

// ---------------------------------------------------------------------------
// K3: out = att @ W^T + bias via mma.sync bf16 split-precision. 128x128 tiles.
// ---------------------------------------------------------------------------
__global__ __launch_bounds__(256, 2) void proj_kernel(const float* __restrict__ bias,
                                                      float* __restrict__ out) {
    extern __shared__ char sm[];
    enum { AHI = 0, ALO = 16384, WHI = 32768, WLO = 49152 };  // 64KB
    const int tid = threadIdx.x, w = tid >> 5, lane = tid & 31;
    const uint32_t smb = smem_u32(sm);
    const int m0 = blockIdx.x * 128, o0 = blockIdx.y * 128;
    const int r0 = w * 16;

    const int a_r = (lane & 7) + ((lane & 8) ? 8 : 0);
    const int a_c = (lane & 16) ? 8 : 0;
    const int b_r = (lane & 7) + ((lane & 16) ? 8 : 0);
    const int b_c = (lane & 8) ? 8 : 0;

    float S[16][4];
#pragma unroll
    for (int i = 0; i < 16; i++)
#pragma unroll
        for (int e = 0; e < 4; e++) S[i][e] = 0.f;

    for (int kt = 0; kt < Ec / 64; kt++) {
        __syncthreads();
        copy_rows(sm + AHI, g_a_hi + (size_t)m0 * Ec + kt * 64, Ec, tid);
        copy_rows(sm + ALO, g_a_lo + (size_t)m0 * Ec + kt * 64, Ec, tid);
        copy_rows(sm + WHI, g_w_hi + (size_t)o0 * Ec + kt * 64, Ec, tid);
        copy_rows(sm + WLO, g_w_lo + (size_t)o0 * Ec + kt * 64, Ec, tid);
        __syncthreads();
#pragma unroll
        for (int ks = 0; ks < 4; ks++) {
            int k0 = ks * 16;
            uint32_t ah[4], al[4];
            ldsm4(ah, smb + AHI + sw64(r0 + a_r, k0 + a_c));
            ldsm4(al, smb + ALO + sw64(r0 + a_r, k0 + a_c));
#pragma unroll
            for (int nb2 = 0; nb2 < 8; nb2++) {
                int n0 = nb2 * 16;
                uint32_t wh_[4], wl_[4];
                ldsm4(wh_, smb + WHI + sw64(n0 + b_r, k0 + b_c));
                ldsm4(wl_, smb + WLO + sw64(n0 + b_r, k0 + b_c));
                mma_bf16(S[2 * nb2],     ah, wh_);
                mma_bf16(S[2 * nb2],     al, wh_);
                mma_bf16(S[2 * nb2],     ah, wl_);
                mma_bf16(S[2 * nb2 + 1], ah, wh_ + 2);
                mma_bf16(S[2 * nb2 + 1], al, wh_ + 2);
                mma_bf16(S[2 * nb2 + 1], ah, wl_ + 2);
            }
        }
    }

    const int row = m0 + r0 + (lane >> 2);
    const int c0 = 2 * (lane & 3);
#pragma unroll
    for (int nb = 0; nb < 16; nb++) {
        int og = o0 + nb * 8 + c0;
        float b0v = bias[og], b1v = bias[og + 1];
        float2 y0 = make_float2(S[nb][0] + b0v, S[nb][1] + b1v);
        float2 y1 = make_float2(S[nb][2] + b0v, S[nb][3] + b1v);
        *(float2*)(out + (size_t)row * Ec + og) = y0;
        *(float2*)(out + (size_t)(row + 8) * Ec + og) = y1;
    }
}

// ---------------------------------------------------------------------------
extern "C" void kernel_launch(void* const* d_in, const int* in_sizes, int n_in,
                              void* d_out, int out_size) {
    const float* q  = (const float*)d_in[0];
    const float* k  = (const float*)d_in[1];
    const float* v  = (const float*)d_in[2];
    const float* qs = (const float*)d_in[3];
    const float* ks = (const float*)d_in[4];
    const float* pw = (const float*)d_in[5];
    const float* pb = (const float*)d_in[6];
    float* out = (float*)d_out;

    prep_kernel<<<(Bc * Nc * Hc) / 8, 256>>>(q, k, v, qs, ks);
    wprep_kernel<<<(Ec * Ec / 2 + 255) / 256, 256>>>(pw);

    int smemA = 163840;  // 160KB
    cudaFuncSetAttribute(attn_kernel, cudaFuncAttributeMaxDynamicSharedMemorySize, smemA);
    attn_kernel<<<dim3(Nc / 128, BHc), 256, smemA>>>();

    int smemP = 65536;   // 64KB
    cudaFuncSetAttribute(proj_kernel, cudaFuncAttributeMaxDynamicSharedMemorySize, smemP);
    proj_kernel<<<dim3((Bc * Nc) / 128, Ec / 128), 256, smemP>>>(pb, out);
}

// round 17
// speedup vs baseline: 1.5758x; 1.0488x over previous
#include <cuda_runtime.h>
#include <cuda_bf16.h>
#include <math.h>
#include <stdint.h>

namespace {
constexpr int Bc = 4, Nc = 2048, Ec = 768, Hc = 12, Dc = 64;
constexpr int BHc = Bc * Hc;  // 48
}

// Scratch (allocation-free rule: __device__ globals)
__device__ __align__(256) __nv_bfloat16 g_q_hi[(size_t)BHc * Nc * Dc];
__device__ __align__(256) __nv_bfloat16 g_q_lo[(size_t)BHc * Nc * Dc];
__device__ __align__(256) __nv_bfloat16 g_k_hi[(size_t)BHc * Nc * Dc];
__device__ __align__(256) __nv_bfloat16 g_k_lo[(size_t)BHc * Nc * Dc];
__device__ __align__(256) __nv_bfloat16 g_v_hi[(size_t)BHc * Nc * Dc];
__device__ __align__(256) __nv_bfloat16 g_v_lo[(size_t)BHc * Nc * Dc];
__device__ __align__(256) __nv_bfloat16 g_a_hi[(size_t)Bc * Nc * Ec];
__device__ __align__(256) __nv_bfloat16 g_a_lo[(size_t)Bc * Nc * Ec];
__device__ __align__(256) __nv_bfloat16 g_w_hi[(size_t)Ec * Ec];
__device__ __align__(256) __nv_bfloat16 g_w_lo[(size_t)Ec * Ec];

// ---------------- helpers ----------------
__device__ __forceinline__ uint32_t smem_u32(const void* p) {
    uint32_t a;
    asm("{ .reg .u64 t; cvta.to.shared.u64 t, %1; cvt.u32.u64 %0, t; }" : "=r"(a) : "l"(p));
    return a;
}
__device__ __forceinline__ float ex2(float x) {
    float r; asm("ex2.approx.ftz.f32 %0, %1;" : "=f"(r) : "f"(x)); return r;
}
// pack (lo,hi) floats into bf16x2: lo -> bits[0:16), hi -> bits[16:32)
__device__ __forceinline__ uint32_t bf16x2_of(float lo, float hi) {
    uint32_t r;
    asm("cvt.rn.bf16x2.f32 %0, %1, %2;" : "=r"(r) : "f"(hi), "f"(lo));
    return r;
}
__device__ __forceinline__ float lo16f(uint32_t h) { return __uint_as_float(h << 16); }
__device__ __forceinline__ float hi16f(uint32_t h) { return __uint_as_float(h & 0xffff0000u); }

__device__ __forceinline__ void ldsm4(uint32_t* r, uint32_t a) {
    asm volatile("ldmatrix.sync.aligned.m8n8.x4.shared.b16 {%0,%1,%2,%3}, [%4];"
                 : "=r"(r[0]), "=r"(r[1]), "=r"(r[2]), "=r"(r[3]) : "r"(a));
}
__device__ __forceinline__ void ldsm4t(uint32_t* r, uint32_t a) {
    asm volatile("ldmatrix.sync.aligned.m8n8.x4.trans.shared.b16 {%0,%1,%2,%3}, [%4];"
                 : "=r"(r[0]), "=r"(r[1]), "=r"(r[2]), "=r"(r[3]) : "r"(a));
}
__device__ __forceinline__ void mma_bf16(float* d, const uint32_t* a, const uint32_t* b) {
    asm volatile("mma.sync.aligned.m16n8k16.row.col.f32.bf16.bf16.f32 "
                 "{%0,%1,%2,%3}, {%4,%5,%6,%7}, {%8,%9}, {%0,%1,%2,%3};"
                 : "+f"(d[0]), "+f"(d[1]), "+f"(d[2]), "+f"(d[3])
                 : "r"(a[0]), "r"(a[1]), "r"(a[2]), "r"(a[3]), "r"(b[0]), "r"(b[1]));
}
__device__ __forceinline__ void cpa16(uint32_t d, const void* g) {
    asm volatile("cp.async.cg.shared.global [%0], [%1], 16;" :: "r"(d), "l"(g) : "memory");
}

// swizzled byte offsets: 64-col bf16 tile (128B rows) and 128-col (256B rows)
__device__ __forceinline__ int sw64(int row, int col) {
    return row * 128 + ((((col >> 3) ^ row) & 7) << 4) + ((col & 7) << 1);
}
__device__ __forceinline__ int sw128(int row, int col) {
    int c = col >> 3;
    return row * 256 + (((c & 8) | ((c ^ row) & 7)) << 4) + ((col & 7) << 1);
}

// 128 rows x 64 bf16 (128B rows) into swizzled smem; coalesced + conflict-free
__device__ __forceinline__ void copy_rows(char* dst, const __nv_bfloat16* src,
                                          int stride, int tid) {
#pragma unroll
    for (int it = 0; it < 4; it++) {
        int u = it * 256 + tid;
        int r = u >> 3, c = u & 7;
        uint4 x = *(const uint4*)(src + (size_t)r * stride + c * 8);
        *(uint4*)(dst + r * 128 + (((c ^ r) & 7) << 4)) = x;
    }
}

// ---------------------------------------------------------------------------
// K1: RMSNorm + xPos RoPE; bf16 hi/lo split for q,k,v; layout [bh][n][d].
// Folds (1/sqrt(D)) * log2(e) into Q (exp2 softmax).
// ---------------------------------------------------------------------------
__global__ void prep_kernel(const float* __restrict__ q, const float* __restrict__ k,
                            const float* __restrict__ v,
                            const float* __restrict__ qs, const float* __restrict__ ks) {
    int w = (blockIdx.x * blockDim.x + threadIdx.x) >> 5;
    int lane = threadIdx.x & 31;
    if (w >= Bc * Nc * Hc) return;
    int h = w % Hc, bn = w / Hc, n = bn % Nc, b = bn / Nc;
    size_t in_off = (size_t)bn * Ec + h * Dc;
    int d0 = lane, d1 = lane + 32;

    float q0 = q[in_off + d0], q1 = q[in_off + d1];
    float k0 = k[in_off + d0], k1 = k[in_off + d1];
    float v0 = v[in_off + d0], v1 = v[in_off + d1];

    float sq = q0 * q0 + q1 * q1, sk = k0 * k0 + k1 * k1;
#pragma unroll
    for (int o = 16; o; o >>= 1) {
        sq += __shfl_xor_sync(0xffffffffu, sq, o);
        sk += __shfl_xor_sync(0xffffffffu, sk, o);
    }
    float qn = rsqrtf(sq * (1.0f / 64.0f) + 1e-6f);
    float kn = rsqrtf(sk * (1.0f / 64.0f) + 1e-6f);
    q0 *= qs[d0] * qn; q1 *= qs[d1] * qn;
    k0 *= ks[d0] * kn; k1 *= ks[d1] * kn;

    int p = d0 >> 1;
    double invf = pow(10000.0, -(double)p / 16.0);
    double fr = (double)n * invf;
    float c = (float)cos(fr), s = (float)sin(fr);
    float sc = (float)pow((2.0 * p + 12.8) / 44.8, ((double)n - 1024.0) / 512.0);
    float qp_ = __shfl_xor_sync(0xffffffffu, q0, 1);
    float kp_ = __shfl_xor_sync(0xffffffffu, k0, 1);
    float sgn = (d0 & 1) ? s : -s;
    q0 = (q0 * c + qp_ * sgn) * sc;
    k0 = (k0 * c + kp_ * sgn) / sc;

    const float QSCL = 0.125f * 1.4426950408889634f;
    q0 *= QSCL; q1 *= QSCL;

    size_t oo = (((size_t)(b * Hc + h)) * Nc + n) * Dc;
    __nv_bfloat16 a;
    a = __float2bfloat16(q0); g_q_hi[oo + d0] = a; g_q_lo[oo + d0] = __float2bfloat16(q0 - __bfloat162float(a));
    a = __float2bfloat16(q1); g_q_hi[oo + d1] = a; g_q_lo[oo + d1] = __float2bfloat16(q1 - __bfloat162float(a));
    a = __float2bfloat16(k0); g_k_hi[oo + d0] = a; g_k_lo[oo + d0] = __float2bfloat16(k0 - __bfloat162float(a));
    a = __float2bfloat16(k1); g_k_hi[oo + d1] = a; g_k_lo[oo + d1] = __float2bfloat16(k1 - __bfloat162float(a));
    a = __float2bfloat16(v0); g_v_hi[oo + d0] = a; g_v_lo[oo + d0] = __float2bfloat16(v0 - __bfloat162float(a));
    a = __float2bfloat16(v1); g_v_hi[oo + d1] = a; g_v_lo[oo + d1] = __float2bfloat16(v1 - __bfloat162float(a));
}

// K1b: W bf16 hi/lo split
__global__ void wprep_kernel(const float* __restrict__ w) {
    int idx = blockIdx.x * blockDim.x + threadIdx.x;
    if (idx >= Ec * Ec / 2) return;
    float x0 = w[2 * idx], x1 = w[2 * idx + 1];
    uint32_t h2 = bf16x2_of(x0, x1);
    ((uint32_t*)g_w_hi)[idx] = h2;
    ((uint32_t*)g_w_lo)[idx] = bf16x2_of(x0 - lo16f(h2), x1 - hi16f(h2));
}

// ---------------------------------------------------------------------------
// K2 v2: causal flash attention, mma.sync bf16 split-precision.
// 512 threads = 16 warps: warp (wr, wc) owns S rows [16wr,16wr+16),
// cols/j-range [64wc, 64wc+64). cp.async double-buffered K/V tiles.
// Partial O / l combined once in the epilogue through smem.
// ---------------------------------------------------------------------------
__global__ __launch_bounds__(512, 1) void attn_kernel() {
    extern __shared__ char sm[];
    enum { QHI = 0, QLO = 16384, STG = 32768, STG_SZ = 65536,
           KOF = 0, KLOF = 16384, VOF = 32768, VLOF = 49152,
           PHI = 163840, PLO = 196608 };               // total 224KB
    const int tid = threadIdx.x, wid = tid >> 5, lane = tid & 31;
    const int wr = wid >> 1, wc = wid & 1;
    const uint32_t smb = smem_u32(sm);
    const int qi = 15 - (int)blockIdx.y;   // big tiles first within each wave
    const int bh = blockIdx.x;
    const size_t hb = (size_t)bh * Nc * Dc;
    const int r0 = wr * 16;

    // ldmatrix per-lane addressing offsets
    const int a_r = (lane & 7) + ((lane & 8) ? 8 : 0);   // A / Vt row group
    const int a_c = (lane & 16) ? 8 : 0;                  // A / Vt col group
    const int b_r = (lane & 7) + ((lane & 16) ? 8 : 0);  // B (K) row group
    const int b_c = (lane & 8) ? 8 : 0;                   // B (K) col group

    // Q tile (plain load, once)
#pragma unroll
    for (int it = 0; it < 2; it++) {
        int u = it * 512 + tid;
        int r = u >> 3, c = u & 7;
        uint32_t dof = r * 128 + (((c ^ r) & 7) << 4);
        size_t so = (size_t)r * Dc + c * 8;
        *(uint4*)(sm + QHI + dof) = *(const uint4*)(g_q_hi + hb + (size_t)qi * 128 * Dc + so);
        *(uint4*)(sm + QLO + dof) = *(const uint4*)(g_q_lo + hb + (size_t)qi * 128 * Dc + so);
    }

    // async K/V tile fill into stage s
    auto fill = [&](int stage, int kt) {
        const __nv_bfloat16* kh = g_k_hi + hb + (size_t)kt * 128 * Dc;
        const __nv_bfloat16* kl = g_k_lo + hb + (size_t)kt * 128 * Dc;
        const __nv_bfloat16* vh = g_v_hi + hb + (size_t)kt * 128 * Dc;
        const __nv_bfloat16* vl = g_v_lo + hb + (size_t)kt * 128 * Dc;
        uint32_t sb = smb + STG + stage * STG_SZ;
#pragma unroll
        for (int it = 0; it < 2; it++) {
            int u = it * 512 + tid;
            int r = u >> 3, c = u & 7;
            uint32_t dof = r * 128 + (((c ^ r) & 7) << 4);
            size_t so = (size_t)r * Dc + c * 8;
            cpa16(sb + KOF + dof, kh + so);
            cpa16(sb + KLOF + dof, kl + so);
            cpa16(sb + VOF + dof, vh + so);
            cpa16(sb + VLOF + dof, vl + so);
        }
        asm volatile("cp.async.commit_group;" ::: "memory");
    };

    fill(0, 0);

    float O[8][4];
#pragma unroll
    for (int i = 0; i < 8; i++)
#pragma unroll
        for (int e = 0; e < 4; e++) O[i][e] = 0.f;
    float lr0 = 0.f, lr1 = 0.f;

    const int rl0 = r0 + (lane >> 2), rl1 = r0 + (lane >> 2) + 8;
    const int c0 = 2 * (lane & 3);

    for (int kt = 0; kt <= qi; kt++) {
        const bool more = (kt + 1 <= qi);
        if (more) fill((kt + 1) & 1, kt + 1);
        if (more) asm volatile("cp.async.wait_group 1;" ::: "memory");
        else      asm volatile("cp.async.wait_group 0;" ::: "memory");
        __syncthreads();

        const uint32_t sb = smb + STG + (kt & 1) * STG_SZ;

        // ---- S = Q K^T (16x64 per warp), 3-term split
        float S[8][4];
#pragma unroll
        for (int i = 0; i < 8; i++)
#pragma unroll
            for (int e = 0; e < 4; e++) S[i][e] = 0.f;

#pragma unroll
        for (int ks = 0; ks < 4; ks++) {
            int k0 = ks * 16;
            uint32_t ah[4], al[4];
            ldsm4(ah, smb + QHI + sw64(r0 + a_r, k0 + a_c));
            ldsm4(al, smb + QLO + sw64(r0 + a_r, k0 + a_c));
#pragma unroll
            for (int nb2 = 0; nb2 < 4; nb2++) {
                int n0 = 64 * wc + nb2 * 16;
                uint32_t kh_[4], kl_[4];
                ldsm4(kh_, sb + KOF + sw64(n0 + b_r, k0 + b_c));
                ldsm4(kl_, sb + KLOF + sw64(n0 + b_r, k0 + b_c));
                mma_bf16(S[2 * nb2],     ah, kh_);
                mma_bf16(S[2 * nb2],     al, kh_);
                mma_bf16(S[2 * nb2],     ah, kl_);
                mma_bf16(S[2 * nb2 + 1], ah, kh_ + 2);
                mma_bf16(S[2 * nb2 + 1], al, kh_ + 2);
                mma_bf16(S[2 * nb2 + 1], ah, kl_ + 2);
            }
        }

        // ---- exp2 softmax (no max), mask diag, split P to bf16 hi/lo in smem
        const bool diag = (kt == qi);
#pragma unroll
        for (int nb = 0; nb < 8; nb++) {
            int cg = 64 * wc + nb * 8 + c0;
            float p00 = ex2(S[nb][0]);
            float p01 = ex2(S[nb][1]);
            float p10 = ex2(S[nb][2]);
            float p11 = ex2(S[nb][3]);
            if (diag) {
                if (cg     > rl0) p00 = 0.f;
                if (cg + 1 > rl0) p01 = 0.f;
                if (cg     > rl1) p10 = 0.f;
                if (cg + 1 > rl1) p11 = 0.f;
            }
            lr0 += p00 + p01;
            lr1 += p10 + p11;
            uint32_t h0 = bf16x2_of(p00, p01);
            uint32_t l0 = bf16x2_of(p00 - lo16f(h0), p01 - hi16f(h0));
            uint32_t h1 = bf16x2_of(p10, p11);
            uint32_t l1 = bf16x2_of(p10 - lo16f(h1), p11 - hi16f(h1));
            *(uint32_t*)(sm + PHI + sw128(rl0, cg)) = h0;
            *(uint32_t*)(sm + PLO + sw128(rl0, cg)) = l0;
            *(uint32_t*)(sm + PHI + sw128(rl1, cg)) = h1;
            *(uint32_t*)(sm + PLO + sw128(rl1, cg)) = l1;
        }
        __syncwarp();   // warp reads exactly the P block it wrote

        // ---- O += P V over this warp's j-range, 3-term split, Vt via trans
#pragma unroll
        for (int ks = 0; ks < 4; ks++) {
            int j0 = 64 * wc + ks * 16;
            uint32_t ph[4], pl[4];
            ldsm4(ph, smb + PHI + sw128(r0 + a_r, j0 + a_c));
            ldsm4(pl, smb + PLO + sw128(r0 + a_r, j0 + a_c));
#pragma unroll
            for (int db2 = 0; db2 < 4; db2++) {
                int d0 = db2 * 16;
                uint32_t vh_[4], vl_[4];
                ldsm4t(vh_, sb + VOF + sw64(j0 + a_r, d0 + a_c));
                ldsm4t(vl_, sb + VLOF + sw64(j0 + a_r, d0 + a_c));
                mma_bf16(O[2 * db2],     ph, vh_);
                mma_bf16(O[2 * db2],     pl, vh_);
                mma_bf16(O[2 * db2],     ph, vl_);
                mma_bf16(O[2 * db2 + 1], ph, vh_ + 2);
                mma_bf16(O[2 * db2 + 1], pl, vh_ + 2);
                mma_bf16(O[2 * db2 + 1], ph, vl_ + 2);
            }
        }
        __syncthreads();   // all reads of this stage + P done before overwrite
    }

    // ---- epilogue: combine the two col-half partials (O, l) via smem
    lr0 += __shfl_xor_sync(0xffffffffu, lr0, 1);
    lr0 += __shfl_xor_sync(0xffffffffu, lr0, 2);
    lr1 += __shfl_xor_sync(0xffffffffu, lr1, 1);
    lr1 += __shfl_xor_sync(0xffffffffu, lr1, 2);

    float* Osc = (float*)(sm + PHI);           // [128][68] padded fp32
    float* Lsc = (float*)(sm + PLO + 4096);    // [128] fp32
    if (wc == 1) {
#pragma unroll
        for (int nb = 0; nb < 8; nb++) {
            int d = nb * 8 + c0;
            Osc[rl0 * 68 + d] = O[nb][0]; Osc[rl0 * 68 + d + 1] = O[nb][1];
            Osc[rl1 * 68 + d] = O[nb][2]; Osc[rl1 * 68 + d + 1] = O[nb][3];
        }
        if ((lane & 3) == 0) { Lsc[rl0] = lr0; Lsc[rl1] = lr1; }
    }
    __syncthreads();
    if (wc == 0) {
        float inv0 = 1.f / (lr0 + Lsc[rl0]);
        float inv1 = 1.f / (lr1 + Lsc[rl1]);
        const int bb = bh / Hc, hh = bh % Hc;
        const int rg0 = qi * 128 + rl0;
#pragma unroll
        for (int nb = 0; nb < 8; nb++) {
            int d = nb * 8 + c0;
            float y00 = (O[nb][0] + Osc[rl0 * 68 + d])     * inv0;
            float y01 = (O[nb][1] + Osc[rl0 * 68 + d + 1]) * inv0;
            float y10 = (O[nb][2] + Osc[rl1 * 68 + d])     * inv1;
            float y11 = (O[nb][3] + Osc[rl1 * 68 + d + 1]) * inv1;
            uint32_t h0 = bf16x2_of(y00, y01);
            uint32_t l0 = bf16x2_of(y00 - lo16f(h0), y01 - hi16f(h0));
            uint32_t h1 = bf16x2_of(y10, y11);
            uint32_t l1 = bf16x2_of(y10 - lo16f(h1), y11 - hi16f(h1));
            size_t off0 = (size_t)(bb * Nc + rg0) * Ec + hh * 64 + d;
            size_t off1 = (size_t)(bb * Nc + rg0 + 8) * Ec + hh * 64 + d;
            *(uint32_t*)(g_a_hi + off0) = h0;
            *(uint32_t*)(g_a_lo + off0) = l0;
            *(uint32_t*)(g_a_hi + off1) = h1;
            *(uint32_t*)(g_a_lo + off1) = l1;
        }
    }
}

// ---------------------------------------------------------------------------
// K3: out = att @ W^T + bias via mma.sync bf16 split-precision. 128x128 tiles.
// ---------------------------------------------------------------------------
__global__ __launch_bounds__(256, 2) void proj_kernel(const float* __restrict__ bias,
                                                      float* __restrict__ out) {
    extern __shared__ char sm[];
    enum { AHI = 0, ALO = 16384, WHI = 32768, WLO = 49152 };  // 64KB
    const int tid = threadIdx.x, w = tid >> 5, lane = tid & 31;
    const uint32_t smb = smem_u32(sm);
    const int m0 = blockIdx.x * 128, o0 = blockIdx.y * 128;
    const int r0 = w * 16;

    const int a_r = (lane & 7) + ((lane & 8) ? 8 : 0);
    const int a_c = (lane & 16) ? 8 : 0;
    const int b_r = (lane & 7) + ((lane & 16) ? 8 : 0);
    const int b_c = (lane & 8) ? 8 : 0;

    float S[16][4];
#pragma unroll
    for (int i = 0; i < 16; i++)
#pragma unroll
        for (int e = 0; e < 4; e++) S[i][e] = 0.f;

    for (int kt = 0; kt < Ec / 64; kt++) {
        __syncthreads();
        copy_rows(sm + AHI, g_a_hi + (size_t)m0 * Ec + kt * 64, Ec, tid);
        copy_rows(sm + ALO, g_a_lo + (size_t)m0 * Ec + kt * 64, Ec, tid);
        copy_rows(sm + WHI, g_w_hi + (size_t)o0 * Ec + kt * 64, Ec, tid);
        copy_rows(sm + WLO, g_w_lo + (size_t)o0 * Ec + kt * 64, Ec, tid);
        __syncthreads();
#pragma unroll
        for (int ks = 0; ks < 4; ks++) {
            int k0 = ks * 16;
            uint32_t ah[4], al[4];
            ldsm4(ah, smb + AHI + sw64(r0 + a_r, k0 + a_c));
            ldsm4(al, smb + ALO + sw64(r0 + a_r, k0 + a_c));
#pragma unroll
            for (int nb2 = 0; nb2 < 8; nb2++) {
                int n0 = nb2 * 16;
                uint32_t wh_[4], wl_[4];
                ldsm4(wh_, smb + WHI + sw64(n0 + b_r, k0 + b_c));
                ldsm4(wl_, smb + WLO + sw64(n0 + b_r, k0 + b_c));
                mma_bf16(S[2 * nb2],     ah, wh_);
                mma_bf16(S[2 * nb2],     al, wh_);
                mma_bf16(S[2 * nb2],     ah, wl_);
                mma_bf16(S[2 * nb2 + 1], ah, wh_ + 2);
                mma_bf16(S[2 * nb2 + 1], al, wh_ + 2);
                mma_bf16(S[2 * nb2 + 1], ah, wl_ + 2);
            }
        }
    }

    const int row = m0 + r0 + (lane >> 2);
    const int c0 = 2 * (lane & 3);
#pragma unroll
    for (int nb = 0; nb < 16; nb++) {
        int og = o0 + nb * 8 + c0;
        float b0v = bias[og], b1v = bias[og + 1];
        float2 y0 = make_float2(S[nb][0] + b0v, S[nb][1] + b1v);
        float2 y1 = make_float2(S[nb][2] + b0v, S[nb][3] + b1v);
        *(float2*)(out + (size_t)row * Ec + og) = y0;
        *(float2*)(out + (size_t)(row + 8) * Ec + og) = y1;
    }
}

// ---------------------------------------------------------------------------
extern "C" void kernel_launch(void* const* d_in, const int* in_sizes, int n_in,
                              void* d_out, int out_size) {
    const float* q  = (const float*)d_in[0];
    const float* k  = (const float*)d_in[1];
    const float* v  = (const float*)d_in[2];
    const float* qs = (const float*)d_in[3];
    const float* ks = (const float*)d_in[4];
    const float* pw = (const float*)d_in[5];
    const float* pb = (const float*)d_in[6];
    float* out = (float*)d_out;

    prep_kernel<<<(Bc * Nc * Hc) / 8, 256>>>(q, k, v, qs, ks);
    wprep_kernel<<<(Ec * Ec / 2 + 255) / 256, 256>>>(pw);

    int smemA = 229376;  // 224KB
    cudaFuncSetAttribute(attn_kernel, cudaFuncAttributeMaxDynamicSharedMemorySize, smemA);
    attn_kernel<<<dim3(BHc, 16), 512, smemA>>>();

    int smemP = 65536;   // 64KB
    cudaFuncSetAttribute(proj_kernel, cudaFuncAttributeMaxDynamicSharedMemorySize, smemP);
    proj_kernel<<<dim3((Bc * Nc) / 128, Ec / 128), 256, smemP>>>(pb, out);
}